// round 17
// baseline (speedup 1.0000x reference)
#include <cuda_runtime.h>
#include <cuda_bf16.h>
#include <cstdint>

#define BATCH 2
#define LSEQ 4096
#define DMODEL 768
#define HDIM 128
#define FLEN 2049
#define INV_SQRT_DK 0.08838834764831845f
#define GEPS 1e-9f
#define PI_F 3.14159265358979323846f

// ---------------- scratch ----------------
__device__ float  g_q [BATCH*HDIM*LSEQ];
__device__ float  g_k [BATCH*HDIM*LSEQ];
__device__ float2 g_Qf[BATCH*HDIM*FLEN];
__device__ float2 g_Kf[BATCH*HDIM*FLEN];
__device__ float  g_ReT[2*BATCH*FLEN*HDIM];
__device__ float  g_zq[BATCH*FLEN];
__device__ float  g_zk[BATCH*FLEN];
__device__ __nv_bfloat16 g_qf_bf[BATCH*HDIM*LSEQ];
__device__ __nv_bfloat16 g_kf_bf[BATCH*HDIM*LSEQ];
__device__ __nv_bfloat16 g_kfc [BATCH*HDIM*LSEQ];   // globally compacted kf (pass 1)
__device__ __nv_bfloat16 g_kfc2[BATCH*HDIM*LSEQ];   // tile-compacted kf (pass 2)
__device__ int    g_colidx[BATCH*LSEQ];             // global compaction indices
__device__ int    g_colloc[BATCH*LSEQ];             // per-tile local col of compacted pos
__device__ int    g_tilecnt[BATCH*32];
__device__ int    g_ncols[BATCH];
__device__ float  g_rowsum[BATCH*LSEQ];

__device__ __forceinline__ uint32_t sptr(const void* p) {
    return (uint32_t)__cvta_generic_to_shared(p);
}
__device__ __forceinline__ void cp16(void* smem_dst, const void* gmem_src) {
    asm volatile("cp.async.ca.shared.global [%0], [%1], 16;"
                 :: "r"(sptr(smem_dst)), "l"(gmem_src));
}

// ---------------- mask compaction: global (pass 1) ----------------
__global__ __launch_bounds__(1024) void compact_mask(const int* __restrict__ mask)
{
    __shared__ int sums[1024];
    const int b = blockIdx.x;
    const int tid = threadIdx.x;
    const int* m = mask + (size_t)b * LSEQ;

    int loc[4], s = 0;
    #pragma unroll
    for (int i = 0; i < 4; i++) {
        loc[i] = (m[tid * 4 + i] != 0);
        s += loc[i];
    }
    sums[tid] = s;
    __syncthreads();
    for (int off = 1; off < 1024; off <<= 1) {
        int v = (tid >= off) ? sums[tid - off] : 0;
        __syncthreads();
        sums[tid] += v;
        __syncthreads();
    }
    int pos = sums[tid] - s;
    #pragma unroll
    for (int i = 0; i < 4; i++) {
        if (loc[i]) g_colidx[b * LSEQ + pos++] = tid * 4 + i;
    }
    if (tid == 1023) g_ncols[b] = sums[1023];
}

// ---------------- mask compaction: per 128-col tile (pass 2) ----------------
__global__ __launch_bounds__(128) void compact_tile(const int* __restrict__ mask)
{
    __shared__ int pre[128];
    const int t = blockIdx.x, b = blockIdx.y;
    const int tid = threadIdx.x;
    const int* m = mask + (size_t)b * LSEQ + t * 128;
    int v = (m[tid] != 0);
    pre[tid] = v;
    __syncthreads();
    for (int off = 1; off < 128; off <<= 1) {
        int x = (tid >= off) ? pre[tid - off] : 0;
        __syncthreads();
        pre[tid] += x;
        __syncthreads();
    }
    if (v) g_colloc[b * LSEQ + t * 128 + pre[tid] - 1] = tid;
    if (tid == 127) g_tilecnt[b * 32 + t] = pre[127];
}

// ---------------- gathers ----------------
__global__ __launch_bounds__(256) void gather_kfc()
{
    const int b = blockIdx.z;
    const int d = blockIdx.y;
    const int i0 = blockIdx.x * 256 + threadIdx.x;
    const int nc = g_ncols[b];
    __nv_bfloat16 v = __float2bfloat16(0.f);
    if (i0 < nc) v = g_kf_bf[((size_t)(b * HDIM + d)) * LSEQ + g_colidx[b * LSEQ + i0]];
    g_kfc[((size_t)(b * HDIM + d)) * LSEQ + i0] = v;
}

__global__ __launch_bounds__(128) void gather_kfc2()
{
    const int t = blockIdx.x;
    const int d = blockIdx.y;
    const int b = blockIdx.z;
    const int j = threadIdx.x;
    const int cnt = g_tilecnt[b * 32 + t];
    __nv_bfloat16 v = __float2bfloat16(0.f);
    if (j < cnt)
        v = g_kf_bf[((size_t)(b * HDIM + d)) * LSEQ + t * 128 + g_colloc[b * LSEQ + t * 128 + j]];
    g_kfc2[((size_t)(b * HDIM + d)) * LSEQ + t * 128 + j] = v;
}

// ---------------- projection GEMM: tf32 mma + 3-stage cp.async ----------------
#define PROJ_STAGES 3
#define PROJ_BK 32
#define PROJ_KP 36
#define PROJ_MAT (128 * PROJ_KP)
#define PROJ_SMEM_FLOATS (PROJ_STAGES * PROJ_MAT * 2)
#define PROJ_SMEM_BYTES (PROJ_SMEM_FLOATS * 4)

__global__ __launch_bounds__(256) void proj_tc(
    const float* __restrict__ query, const float* __restrict__ key,
    const float* __restrict__ Wq, const float* __restrict__ bq,
    const float* __restrict__ Wk, const float* __restrict__ bk)
{
    extern __shared__ float dsm[];
    float* Wbase = dsm;
    float* Xbase = dsm + PROJ_STAGES * PROJ_MAT;

    const int tensor = blockIdx.y;
    const float* X  = tensor ? key : query;
    const float* W  = tensor ? Wk  : Wq;
    const float* bi = tensor ? bk  : bq;
    float* dst = tensor ? g_k : g_q;

    const int l0 = blockIdx.x * 128;
    const int tid  = threadIdx.x;
    const int warp = tid >> 5, lane = tid & 31;
    const int g = lane >> 2, tg = lane & 3;
    const int wd = (warp & 1) * 64;
    const int wn = (warp >> 1) * 32;

    float acc[4][4][4];
    #pragma unroll
    for (int i = 0; i < 4; i++)
        #pragma unroll
        for (int j = 0; j < 4; j++)
            #pragma unroll
            for (int c = 0; c < 4; c++) acc[i][j][c] = 0.f;

    auto load_stage = [&](int kc, int st) {
        const int k0 = kc * PROJ_BK;
        float* Ws = Wbase + st * PROJ_MAT;
        float* Xs = Xbase + st * PROJ_MAT;
        #pragma unroll
        for (int it = 0; it < 4; it++) {
            int idx = tid + 256 * it;
            int row = idx >> 3;
            int seg = (idx & 7) << 2;
            cp16(Ws + row * PROJ_KP + seg, W + (size_t)row * DMODEL + k0 + seg);
            cp16(Xs + row * PROJ_KP + seg, X + (size_t)(l0 + row) * DMODEL + k0 + seg);
        }
        asm volatile("cp.async.commit_group;");
    };

    load_stage(0, 0);
    load_stage(1, 1);

    const int NCHUNK = DMODEL / PROJ_BK;
    #pragma unroll 1
    for (int kc = 0; kc < NCHUNK; kc++) {
        const int st = kc % PROJ_STAGES;
        asm volatile("cp.async.wait_group 1;");
        __syncthreads();
        if (kc + 2 < NCHUNK) load_stage(kc + 2, (kc + 2) % PROJ_STAGES);

        const float* Ws = Wbase + st * PROJ_MAT;
        const float* Xs = Xbase + st * PROJ_MAT;

        #pragma unroll
        for (int ks = 0; ks < 4; ks++) {
            const int k = ks * 8;
            uint32_t a[4][4], bf[4][2];
            #pragma unroll
            for (int i = 0; i < 4; i++) {
                int d = wd + i * 16 + g;
                a[i][0] = __float_as_uint(Ws[(d    ) * PROJ_KP + k + tg    ]);
                a[i][1] = __float_as_uint(Ws[(d + 8) * PROJ_KP + k + tg    ]);
                a[i][2] = __float_as_uint(Ws[(d    ) * PROJ_KP + k + tg + 4]);
                a[i][3] = __float_as_uint(Ws[(d + 8) * PROJ_KP + k + tg + 4]);
            }
            #pragma unroll
            for (int j = 0; j < 4; j++) {
                int n = wn + j * 8 + g;
                bf[j][0] = __float_as_uint(Xs[n * PROJ_KP + k + tg    ]);
                bf[j][1] = __float_as_uint(Xs[n * PROJ_KP + k + tg + 4]);
            }
            #pragma unroll
            for (int i = 0; i < 4; i++)
                #pragma unroll
                for (int j = 0; j < 4; j++) {
                    asm volatile(
                        "mma.sync.aligned.m16n8k8.row.col.f32.tf32.tf32.f32 "
                        "{%0,%1,%2,%3},{%4,%5,%6,%7},{%8,%9},{%0,%1,%2,%3};"
                        : "+f"(acc[i][j][0]), "+f"(acc[i][j][1]),
                          "+f"(acc[i][j][2]), "+f"(acc[i][j][3])
                        : "r"(a[i][0]), "r"(a[i][1]), "r"(a[i][2]), "r"(a[i][3]),
                          "r"(bf[j][0]), "r"(bf[j][1]));
                }
        }
        __syncthreads();
    }

    #pragma unroll
    for (int i = 0; i < 4; i++) {
        int d0 = wd + i * 16 + g;
        float bv0 = bi[d0], bv1 = bi[d0 + 8];
        #pragma unroll
        for (int j = 0; j < 4; j++) {
            int gl = l0 + wn + j * 8 + 2 * tg;
            int b  = gl >> 12;
            int l  = gl & 4095;
            float* o0 = dst + (size_t)((b << 7) + d0    ) * LSEQ + l;
            float* o1 = dst + (size_t)((b << 7) + d0 + 8) * LSEQ + l;
            *(float2*)o0 = make_float2(acc[i][j][0] + bv0, acc[i][j][1] + bv0);
            *(float2*)o1 = make_float2(acc[i][j][2] + bv1, acc[i][j][3] + bv1);
        }
    }
}

// ---------------- radix-4 4096-pt FFT ----------------
#define FFT_NT 512
__device__ __forceinline__ void fill_tw(float2* tw, int tid)
{
    for (int j = tid; j < 1024; j += FFT_NT) {
        float ang = -PI_F * (float)j / 2048.0f;
        float s, c;
        __sincosf(ang, &s, &c);
        tw[j] = make_float2(c, s);
    }
}

__device__ __forceinline__ float2 cmul(float2 a, float2 b) {
    return make_float2(a.x*b.x - a.y*b.y, a.x*b.y + a.y*b.x);
}

__device__ __forceinline__ int dr12(int i) {
    unsigned y = __brev((unsigned)i) >> 20;
    return (int)(((y & 0x555u) << 1) | ((y >> 1) & 0x555u));
}

__device__ __forceinline__ void fft4096_r4(float2* s, const float2* tw, int tid, bool inv)
{
    #pragma unroll 1
    for (int st = 0; st < 6; st++) {
        const int twoSt = 2 * st;
        const int L = 1 << twoSt;
        const int shift = 10 - twoSt;
        #pragma unroll
        for (int tt = 0; tt < 1024 / FFT_NT; tt++) {
            int t = tid + tt * FFT_NT;
            int j  = t & (L - 1);
            int i0 = ((t >> twoSt) << (twoSt + 2)) + j;
            int e  = j << shift;
            float2 w1 = tw[e];
            if (inv) w1.y = -w1.y;
            float2 w2 = cmul(w1, w1);
            float2 w3 = cmul(w1, w2);

            float2 u0 = s[i0];
            float2 u1 = cmul(s[i0 + L],   w1);
            float2 u2 = cmul(s[i0 + 2*L], w2);
            float2 u3 = cmul(s[i0 + 3*L], w3);

            float2 v0 = make_float2(u0.x + u2.x, u0.y + u2.y);
            float2 v1 = make_float2(u0.x - u2.x, u0.y - u2.y);
            float2 v2 = make_float2(u1.x + u3.x, u1.y + u3.y);
            float2 v3 = make_float2(u1.x - u3.x, u1.y - u3.y);

            s[i0]       = make_float2(v0.x + v2.x, v0.y + v2.y);
            s[i0 + 2*L] = make_float2(v0.x - v2.x, v0.y - v2.y);
            if (!inv) {
                s[i0 + L]   = make_float2(v1.x + v3.y, v1.y - v3.x);
                s[i0 + 3*L] = make_float2(v1.x - v3.y, v1.y + v3.x);
            } else {
                s[i0 + L]   = make_float2(v1.x - v3.y, v1.y + v3.x);
                s[i0 + 3*L] = make_float2(v1.x + v3.y, v1.y - v3.x);
            }
        }
        __syncthreads();
    }
}

// forward FFT + zero rowsums (first 16 blocks) + freq-major real parts
__global__ __launch_bounds__(FFT_NT) void fft_fwd_kernel()
{
    __shared__ float2 s[4096];
    __shared__ float2 tw[1024];
    const int blk = blockIdx.x;
    const int tensor = blk >> 7;
    const int pr = blk & 127;
    const int b = pr >> 6;
    const int j = pr & 63;
    const int row0 = b * 128 + 2 * j;
    const float* src0 = (tensor ? g_k : g_q) + (size_t)row0 * LSEQ;
    const float* src1 = src0 + LSEQ;
    float2* dst0 = (tensor ? g_Kf : g_Qf) + (size_t)row0 * FLEN;
    float2* dst1 = dst0 + FLEN;
    float* rt = g_ReT + ((size_t)(tensor * BATCH + b) * FLEN) * HDIM;
    const int tid = threadIdx.x;

    if (blk < 16) g_rowsum[blk * FFT_NT + tid] = 0.f;

    fill_tw(tw, tid);
    for (int i = tid; i < 4096; i += FFT_NT) {
        s[dr12(i)] = make_float2(src0[i], src1[i]);
    }
    __syncthreads();
    fft4096_r4(s, tw, tid, false);

    for (int f = tid; f < FLEN; f += FFT_NT) {
        float2 cf = s[f];
        float2 cn = s[(4096 - f) & 4095];
        float re0 = 0.5f * (cf.x + cn.x);
        float re1 = 0.5f * (cf.y + cn.y);
        dst0[f] = make_float2(re0, 0.5f * (cf.y - cn.y));
        dst1[f] = make_float2(re1, 0.5f * (cn.x - cf.x));
        rt[(size_t)f * HDIM + 2 * j    ] = re0;
        rt[(size_t)f * HDIM + 2 * j + 1] = re1;
    }
}

// ---------------- selector: tf32 tensor-core MLP ----------------
#define SELG_KP 132
#define SELG_AS (64 * SELG_KP)
#define SELG_BS (64 * SELG_KP)
#define SELG_SMEM_BYTES ((SELG_AS + SELG_BS) * 4)

__global__ __launch_bounds__(256) void selector_tc(
    const float* __restrict__ qW1, const float* __restrict__ qb1,
    const float* __restrict__ qW2, const float* __restrict__ qb2,
    const float* __restrict__ kW1, const float* __restrict__ kb1,
    const float* __restrict__ kW2, const float* __restrict__ kb2,
    const float* __restrict__ q_noise, const float* __restrict__ k_noise)
{
    extern __shared__ float ssm[];
    float* As  = ssm;
    float* Bs  = ssm + SELG_AS;
    float* h1s = ssm;
    __shared__ float lgs[64][2];

    const int tile = blockIdx.x;
    const int b = blockIdx.y;
    const int tensor = blockIdx.z;
    const int f0 = tile * 64;
    const float* ReT = g_ReT + ((size_t)(tensor * BATCH + b) * FLEN) * HDIM;
    const float* W1 = tensor ? kW1 : qW1;
    const float* b1 = tensor ? kb1 : qb1;
    const float* W2 = tensor ? kW2 : qW2;
    const float* b2 = tensor ? kb2 : qb2;
    const float* nz = tensor ? k_noise : q_noise;
    float* z = tensor ? g_zk : g_zq;

    const int tid  = threadIdx.x;
    const int warp = tid >> 5, lane = tid & 31;
    const int g = lane >> 2, tg = lane & 3;
    const int wu = (warp & 1) * 32;
    const int wf = (warp >> 1) * 16;

    #pragma unroll
    for (int it = 0; it < 8; it++) {
        int idx = tid + 256 * it;
        int row = idx >> 5;
        int seg = (idx & 31) << 2;
        cp16(As + row * SELG_KP + seg, W1 + row * 128 + seg);
        int f = f0 + row;
        if (f < FLEN) {
            cp16(Bs + row * SELG_KP + seg, ReT + (size_t)f * HDIM + seg);
        } else {
            *(float4*)(Bs + row * SELG_KP + seg) = make_float4(0.f, 0.f, 0.f, 0.f);
        }
    }
    asm volatile("cp.async.commit_group;");
    asm volatile("cp.async.wait_group 0;");
    __syncthreads();

    float acc[2][2][4];
    #pragma unroll
    for (int i = 0; i < 2; i++)
        #pragma unroll
        for (int j = 0; j < 2; j++)
            #pragma unroll
            for (int c = 0; c < 4; c++) acc[i][j][c] = 0.f;

    #pragma unroll
    for (int ks = 0; ks < 16; ks++) {
        const int k = ks * 8;
        uint32_t a[2][4], bf[2][2];
        #pragma unroll
        for (int i = 0; i < 2; i++) {
            int u = wu + i * 16 + g;
            a[i][0] = __float_as_uint(As[(u    ) * SELG_KP + k + tg    ]);
            a[i][1] = __float_as_uint(As[(u + 8) * SELG_KP + k + tg    ]);
            a[i][2] = __float_as_uint(As[(u    ) * SELG_KP + k + tg + 4]);
            a[i][3] = __float_as_uint(As[(u + 8) * SELG_KP + k + tg + 4]);
        }
        #pragma unroll
        for (int j = 0; j < 2; j++) {
            int n = wf + j * 8 + g;
            bf[j][0] = __float_as_uint(Bs[n * SELG_KP + k + tg    ]);
            bf[j][1] = __float_as_uint(Bs[n * SELG_KP + k + tg + 4]);
        }
        #pragma unroll
        for (int i = 0; i < 2; i++)
            #pragma unroll
            for (int j = 0; j < 2; j++) {
                asm volatile(
                    "mma.sync.aligned.m16n8k8.row.col.f32.tf32.tf32.f32 "
                    "{%0,%1,%2,%3},{%4,%5,%6,%7},{%8,%9},{%0,%1,%2,%3};"
                    : "+f"(acc[i][j][0]), "+f"(acc[i][j][1]),
                      "+f"(acc[i][j][2]), "+f"(acc[i][j][3])
                    : "r"(a[i][0]), "r"(a[i][1]), "r"(a[i][2]), "r"(a[i][3]),
                      "r"(bf[j][0]), "r"(bf[j][1]));
            }
    }
    __syncthreads();

    #pragma unroll
    for (int i = 0; i < 2; i++) {
        int u0 = wu + i * 16 + g;
        float bv0 = b1[u0], bv1 = b1[u0 + 8];
        #pragma unroll
        for (int j = 0; j < 2; j++) {
            int f = wf + j * 8 + 2 * tg;
            h1s[(f    ) * 65 + u0    ] = fmaxf(acc[i][j][0] + bv0, 0.f);
            h1s[(f + 1) * 65 + u0    ] = fmaxf(acc[i][j][1] + bv0, 0.f);
            h1s[(f    ) * 65 + u0 + 8] = fmaxf(acc[i][j][2] + bv1, 0.f);
            h1s[(f + 1) * 65 + u0 + 8] = fmaxf(acc[i][j][3] + bv1, 0.f);
        }
    }
    __syncthreads();

    if (tid < 128) {
        int fl = tid >> 1, c = tid & 1;
        int f = f0 + fl;
        if (f < FLEN) {
            float acc2 = b2[c];
            const float* w2 = W2 + c * 64;
            const float* h = h1s + fl * 65;
            #pragma unroll 16
            for (int u = 0; u < 64; u++) acc2 = fmaf(h[u], w2[u], acc2);
            float n = nz[((size_t)b * FLEN + f) * 2 + c];
            lgs[fl][c] = acc2 + (-logf(-logf(n + GEPS) + GEPS));
        }
    }
    __syncthreads();
    if (tid < 64) {
        int f = f0 + tid;
        if (f < FLEN) z[b * FLEN + f] = 1.f / (1.f + expf(lgs[tid][0] - lgs[tid][1]));
    }
}

// inverse FFT; store bf16.
__global__ __launch_bounds__(FFT_NT) void fft_inv_kernel()
{
    __shared__ float2 s[4096];
    __shared__ float2 tw[1024];
    const int blk = blockIdx.x;
    const int tensor = blk >> 7;
    const int pr = blk & 127;
    const int b = pr >> 6;
    const int j = pr & 63;
    const int row0 = b * 128 + 2 * j;
    const float2* src0 = (tensor ? g_Kf : g_Qf) + (size_t)row0 * FLEN;
    const float2* src1 = src0 + FLEN;
    const float* z = (tensor ? g_zk : g_zq) + (size_t)b * FLEN;
    __nv_bfloat16* dst0 = (tensor ? g_kf_bf : g_qf_bf) + (size_t)row0 * LSEQ;
    __nv_bfloat16* dst1 = dst0 + LSEQ;
    const int tid = threadIdx.x;

    fill_tw(tw, tid);
    for (int i = tid; i < 4096; i += FFT_NT) {
        int f = (i <= 2048) ? i : (4096 - i);
        float zz = z[f];
        float2 a = src0[f];
        float2 bb = src1[f];
        if (i > 2048) { a.y = -a.y; bb.y = -bb.y; }
        a.x *= zz; a.y *= zz; bb.x *= zz; bb.y *= zz;
        s[dr12(i)] = make_float2(a.x - bb.y, a.y + bb.x);
    }
    __syncthreads();
    fft4096_r4(s, tw, tid, true);
    const float inv = 1.f / 4096.f;
    for (int i = tid; i < 4096; i += FFT_NT) {
        float2 v = s[i];
        dst0[i] = __float2bfloat16(v.x * inv);
        dst1[i] = __float2bfloat16(v.y * inv);
    }
}

// ---------------- scores GEMM: single-stage full-K smem ----------------
// Pass 1 (WRITE=0): globally compacted columns, 4 m-tiles per block, rowsums.
// Pass 2 (WRITE=1): tile-compacted columns, chunk-skipped mma, scatter epilogue.
#define GSK 136
#define GS_Q 0
#define GS_K (128 * GSK)
#define GEMM_SMEM_BYTES (2 * 128 * GSK * 2)

template<int WRITE>
__global__ __launch_bounds__(256) void gemm_scores_bf16(float* __restrict__ out,
                                                        const int* __restrict__ mask)
{
    extern __shared__ __nv_bfloat16 gsm[];
    __nv_bfloat16* Qs = gsm + GS_Q;
    __nv_bfloat16* Ks = gsm + GS_K;
    float* Dsm = (float*)gsm;                 // pass-2 staging (reuses Qs/Ks)
    __shared__ int cl[128];

    const int NMT = WRITE ? 1 : 4;

    const int b  = blockIdx.z;
    const int l0 = blockIdx.y * 128;
    const __nv_bfloat16* A  = g_qf_bf + (size_t)b * HDIM * LSEQ;
    const __nv_bfloat16* Bm = (WRITE ? g_kfc2 : g_kfc) + (size_t)b * HDIM * LSEQ;
    const int nc = WRITE ? g_tilecnt[b * 32 + blockIdx.x] : g_ncols[b];

    if (!WRITE && blockIdx.x * NMT * 128 >= nc) return;

    const int tid  = threadIdx.x;
    const int warp = tid >> 5, lane = tid & 31;
    const int g = lane >> 2, tg = lane & 3;
    const int wl = (warp & 1) * 64;
    const int wn = (warp >> 1) * 32;
    const bool active = !WRITE || (wn < nc);

    const int lr   = lane & 7;
    const int koff = lr + ((lane & 16) ? 8 : 0);
    const int coff = (lane & 8) ? 8 : 0;
    const int kb   = lr + ((lane & 8) ? 8 : 0);
    const int cb   = (lane & 16) ? 8 : 0;

    if (WRITE && tid < 128) cl[tid] = g_colloc[b * LSEQ + blockIdx.x * 128 + tid];

    // stage A once
    #pragma unroll
    for (int it = 0; it < 8; it++) {
        int idx = tid + 256 * it;
        int k  = idx >> 4;
        int c8 = (idx & 15) << 3;
        cp16(Qs + k * GSK + c8, A + (size_t)k * LSEQ + l0 + c8);
    }

    float rs[4][2];
    #pragma unroll
    for (int i = 0; i < 4; i++) { rs[i][0] = 0.f; rs[i][1] = 0.f; }

    float acc[4][4][4];

    #pragma unroll 1
    for (int mt = 0; mt < NMT; mt++) {
        const int m0 = (blockIdx.x * NMT + mt) * 128;
        if (!WRITE && m0 >= nc) break;

        #pragma unroll
        for (int it = 0; it < 8; it++) {
            int idx = tid + 256 * it;
            int k  = idx >> 4;
            int c8 = (idx & 15) << 3;
            cp16(Ks + k * GSK + c8, Bm + (size_t)k * LSEQ + m0 + c8);
        }
        asm volatile("cp.async.commit_group;");
        asm volatile("cp.async.wait_group 0;");
        __syncthreads();

        #pragma unroll
        for (int i = 0; i < 4; i++)
            #pragma unroll
            for (int j = 0; j < 4; j++)
                #pragma unroll
                for (int c = 0; c < 4; c++) acc[i][j][c] = 0.f;

        if (active) {
            #pragma unroll
            for (int ks = 0; ks < 8; ks++) {
                const int k0 = ks * 16;
                uint32_t a[4][4];
                #pragma unroll
                for (int i = 0; i < 4; i++) {
                    uint32_t addr = sptr(Qs + (k0 + koff) * GSK + wl + 16 * i + coff);
                    asm volatile(
                        "ldmatrix.sync.aligned.m8n8.x4.trans.shared.b16 {%0,%1,%2,%3}, [%4];"
                        : "=r"(a[i][0]), "=r"(a[i][1]), "=r"(a[i][2]), "=r"(a[i][3])
                        : "r"(addr));
                }
                uint32_t bfr[2][4];
                #pragma unroll
                for (int jj = 0; jj < 2; jj++) {
                    uint32_t addr = sptr(Ks + (k0 + kb) * GSK + wn + 16 * jj + cb);
                    asm volatile(
                        "ldmatrix.sync.aligned.m8n8.x4.trans.shared.b16 {%0,%1,%2,%3}, [%4];"
                        : "=r"(bfr[jj][0]), "=r"(bfr[jj][1]), "=r"(bfr[jj][2]), "=r"(bfr[jj][3])
                        : "r"(addr));
                }
                #pragma unroll
                for (int i = 0; i < 4; i++)
                    #pragma unroll
                    for (int j = 0; j < 4; j++) {
                        uint32_t b0 = bfr[j >> 1][2 * (j & 1)];
                        uint32_t b1 = bfr[j >> 1][2 * (j & 1) + 1];
                        asm volatile(
                            "mma.sync.aligned.m16n8k16.row.col.f32.bf16.bf16.f32 "
                            "{%0,%1,%2,%3},{%4,%5,%6,%7},{%8,%9},{%0,%1,%2,%3};"
                            : "+f"(acc[i][j][0]), "+f"(acc[i][j][1]),
                              "+f"(acc[i][j][2]), "+f"(acc[i][j][3])
                            : "r"(a[i][0]), "r"(a[i][1]), "r"(a[i][2]), "r"(a[i][3]),
                              "r"(b0), "r"(b1));
                    }
            }
        }

        if (!WRITE) {
            #pragma unroll
            for (int i = 0; i < 4; i++) {
                #pragma unroll
                for (int j = 0; j < 4; j++) {
                    int col = m0 + wn + j * 8 + 2 * tg;
                    float p00 = (col     < nc) ? __expf(acc[i][j][0] * INV_SQRT_DK) : 0.f;
                    float p01 = (col + 1 < nc) ? __expf(acc[i][j][1] * INV_SQRT_DK) : 0.f;
                    float p10 = (col     < nc) ? __expf(acc[i][j][2] * INV_SQRT_DK) : 0.f;
                    float p11 = (col + 1 < nc) ? __expf(acc[i][j][3] * INV_SQRT_DK) : 0.f;
                    rs[i][0] += p00 + p01;
                    rs[i][1] += p10 + p11;
                }
            }
            if (mt + 1 < NMT) __syncthreads();
        }
    }

    if (!WRITE) {
        #pragma unroll
        for (int i = 0; i < 4; i++) {
            int row0 = l0 + wl + i * 16 + g;
            float rs0 = rs[i][0], rs1 = rs[i][1];
            rs0 += __shfl_xor_sync(0xffffffffu, rs0, 1);
            rs0 += __shfl_xor_sync(0xffffffffu, rs0, 2);
            rs1 += __shfl_xor_sync(0xffffffffu, rs1, 1);
            rs1 += __shfl_xor_sync(0xffffffffu, rs1, 2);
            if (tg == 0) {
                atomicAdd(&g_rowsum[b * LSEQ + row0    ], rs0);
                atomicAdd(&g_rowsum[b * LSEQ + row0 + 8], rs1);
            }
        }
    } else {
        // scatter epilogue: zero staging tile, place normalized probs at original
        // local columns, coalesced write out.
        __syncthreads();                       // all smem reads (mma) done
        for (int i = tid; i < 128 * 132; i += 256) Dsm[i] = 0.f;
        __syncthreads();

        if (active) {
            #pragma unroll
            for (int i = 0; i < 4; i++) {
                int row0 = wl + i * 16 + g;
                float inv0 = 1.f / g_rowsum[b * LSEQ + l0 + row0    ];
                float inv1 = 1.f / g_rowsum[b * LSEQ + l0 + row0 + 8];
                #pragma unroll
                for (int j = 0; j < 4; j++) {
                    int cc = wn + j * 8 + 2 * tg;
                    if (cc < nc) {
                        Dsm[(row0    ) * 132 + cl[cc]] = __expf(acc[i][j][0] * INV_SQRT_DK) * inv0;
                        Dsm[(row0 + 8) * 132 + cl[cc]] = __expf(acc[i][j][2] * INV_SQRT_DK) * inv1;
                    }
                    if (cc + 1 < nc) {
                        Dsm[(row0    ) * 132 + cl[cc + 1]] = __expf(acc[i][j][1] * INV_SQRT_DK) * inv0;
                        Dsm[(row0 + 8) * 132 + cl[cc + 1]] = __expf(acc[i][j][3] * INV_SQRT_DK) * inv1;
                    }
                }
            }
        }
        __syncthreads();

        const int m0 = blockIdx.x * 128;
        #pragma unroll
        for (int it = 0; it < 16; it++) {
            int f = tid + 256 * it;            // float4 id 0..4095
            int r  = f >> 5;                   // 0..127
            int c4 = (f & 31) << 2;            // 0..124
            float4 v = make_float4(Dsm[r * 132 + c4], Dsm[r * 132 + c4 + 1],
                                   Dsm[r * 132 + c4 + 2], Dsm[r * 132 + c4 + 3]);
            *(float4*)(out + ((size_t)b * LSEQ + l0 + r) * LSEQ + m0 + c4) = v;
        }
    }
}

// ---------------- launch ----------------
extern "C" void kernel_launch(void* const* d_in, const int* in_sizes, int n_in,
                              void* d_out, int out_size)
{
    const float* query   = (const float*)d_in[0];
    const float* key     = (const float*)d_in[1];
    const int*   mask    = (const int*)  d_in[2];
    const float* Wq      = (const float*)d_in[3];
    const float* bq      = (const float*)d_in[4];
    const float* Wk      = (const float*)d_in[5];
    const float* bk      = (const float*)d_in[6];
    const float* qW1     = (const float*)d_in[7];
    const float* qb1     = (const float*)d_in[8];
    const float* qW2     = (const float*)d_in[9];
    const float* qb2     = (const float*)d_in[10];
    const float* kW1     = (const float*)d_in[11];
    const float* kb1     = (const float*)d_in[12];
    const float* kW2     = (const float*)d_in[13];
    const float* kb2     = (const float*)d_in[14];
    const float* q_noise = (const float*)d_in[15];
    const float* k_noise = (const float*)d_in[16];
    float* out = (float*)d_out;

    cudaFuncSetAttribute(proj_tc, cudaFuncAttributeMaxDynamicSharedMemorySize,
                         PROJ_SMEM_BYTES);
    cudaFuncSetAttribute(selector_tc, cudaFuncAttributeMaxDynamicSharedMemorySize,
                         SELG_SMEM_BYTES);
    cudaFuncSetAttribute(gemm_scores_bf16<0>, cudaFuncAttributeMaxDynamicSharedMemorySize,
                         GEMM_SMEM_BYTES);
    cudaFuncSetAttribute(gemm_scores_bf16<1>, cudaFuncAttributeMaxDynamicSharedMemorySize,
                         GEMM_SMEM_BYTES);

    compact_mask<<<BATCH, 1024>>>(mask);
    compact_tile<<<dim3(32, BATCH), 128>>>(mask);
    proj_tc<<<dim3(64, 2), 256, PROJ_SMEM_BYTES>>>(query, key, Wq, bq, Wk, bk);
    fft_fwd_kernel<<<256, FFT_NT>>>();
    selector_tc<<<dim3((FLEN + 63) / 64, BATCH, 2), 256, SELG_SMEM_BYTES>>>(
        qW1, qb1, qW2, qb2, kW1, kb1, kW2, kb2, q_noise, k_noise);
    fft_inv_kernel<<<256, FFT_NT>>>();
    gather_kfc<<<dim3(LSEQ / 256, HDIM, BATCH), 256>>>();
    gather_kfc2<<<dim3(32, HDIM, BATCH), 128>>>();
    gemm_scores_bf16<0><<<dim3(8, 32, BATCH), 256, GEMM_SMEM_BYTES>>>(out, mask);
    gemm_scores_bf16<1><<<dim3(32, 32, BATCH), 256, GEMM_SMEM_BYTES>>>(out, mask);
}